// round 14
// baseline (speedup 1.0000x reference)
#include <cuda_runtime.h>
#include <cuda_fp16.h>
#include <cstddef>

#define NB 2
#define NC 128
#define TWOC 256
#define NE 60000
#define TR_BLOCKS (2 * NB * 2 * (NE / 32))          // 15000 transpose tiles
#define W_WARPS   (2 * NC * 15 + 3)
#define W_BLOCKS  ((W_WARPS + 7) / 8)
#define GROUPS2   (NB * NE / 2)                      // 60000 2-edge groups
#define STAGE_BYTES 5120                             // 10 rows x 512B
#define WARP_BUF    (2 * STAGE_BYTES)
#define DATA_BYTES  (8 * WARP_BUF)                   // 81920
#define SMEM_MAIN   (DATA_BYTES + 16 * 8)            // + 16 mbarriers

// Transposed inputs in fp16, tensor-interleaved: [b][e][tensor][c] (512B/edge)
__device__ __half g_xti[(size_t)NB * NE * TWOC];
// Effective fused weights: [branch][c][s*3+k] padded to 16
__device__ float g_V[2][NC][16];
__device__ float g_cb[3];

// ---------------------------------------------------------------------------
// Kernel 1 (fused): transpose x->fp16 interleaved + weight folding.
// ---------------------------------------------------------------------------
__global__ void __launch_bounds__(256)
prep_kernel(const float* __restrict__ x0, const float* __restrict__ x1,
    const float* __restrict__ Wa_local, const float* __restrict__ ba_local,
    const float* __restrict__ Wb_local, const float* __restrict__ bb_local,
    const float* __restrict__ Wa_tri,   const float* __restrict__ ba_tri,
    const float* __restrict__ Wb_tri,   const float* __restrict__ bb_tri,
    const float* __restrict__ Wa_fuse,  const float* __restrict__ ba_fuse,
    const float* __restrict__ Wb_fuse,  const float* __restrict__ bb_fuse)
{
    if (blockIdx.x < TR_BLOCKS) {
        __shared__ __half tile[32][66];
        int bx = blockIdx.x;
        const int eb = bx % (NE / 32);  bx /= (NE / 32);
        const int ch = bx & 1;          bx >>= 1;
        const int b  = bx & 1;
        const int tensor = bx >> 1;
        const float* __restrict__ src = tensor ? x1 : x0;
        const int e0 = eb * 32, c0 = ch * 64;
        const int tx = threadIdx.x & 31;
        const int ty = threadIdx.x >> 5;

#pragma unroll
        for (int i = 0; i < 8; i++) {
            int cl = ty + 8 * i;
            tile[tx][cl] = __float2half_rn(
                src[((size_t)b * NC + c0 + cl) * NE + e0 + tx]);
        }
        __syncthreads();
#pragma unroll
        for (int it = 0; it < 4; it++) {
            int e = ty * 4 + it;
            unsigned v = *reinterpret_cast<const unsigned*>(&tile[e][2 * tx]);
            *reinterpret_cast<unsigned*>(
                g_xti + ((size_t)(b * NE + e0 + e)) * TWOC
                      + tensor * NC + c0 + 2 * tx) = v;
        }
        return;
    }

    const int lane = threadIdx.x & 31;
    const int w = (blockIdx.x - TR_BLOCKS) * 8 + (threadIdx.x >> 5);

    if (w < 2 * NC * 15) {
        const int t   = w / (NC * 15);
        const int rem = w - t * (NC * 15);
        const int c   = rem / 15;
        const int sk  = rem - c * 15;
        const int s   = sk / 3;
        const int k   = sk - s * 3;
        const float* Wf = t ? Wb_fuse  : Wa_fuse;
        const float* Wt = t ? Wb_tri   : Wa_tri;
        const float* Wl = t ? Wb_local : Wa_local;
        float acc = 0.f;
#pragma unroll
        for (int j = 0; j < 4; j++) {
            int o = lane + 32 * j;
            acc = fmaf(Wf[k * (2 * NC) + NC + o], Wt[(o * NC + c) * 5 + s], acc);
            if (s == 0)
                acc = fmaf(Wf[k * (2 * NC) + o], Wl[o * NC + c], acc);
        }
#pragma unroll
        for (int off = 16; off; off >>= 1)
            acc += __shfl_xor_sync(0xffffffffu, acc, off);
        if (lane == 0) {
            g_V[t][c][sk] = acc;
            if (sk == 0) g_V[t][c][15] = 0.f;
        }
    } else if (w < 2 * NC * 15 + 3) {
        const int k = w - 2 * NC * 15;
        float acc = 0.f;
#pragma unroll
        for (int j = 0; j < 4; j++) {
            int o = lane + 32 * j;
            acc = fmaf(Wa_fuse[k * 2 * NC + o],      ba_local[o], acc);
            acc = fmaf(Wa_fuse[k * 2 * NC + NC + o], ba_tri[o],   acc);
            acc = fmaf(Wb_fuse[k * 2 * NC + o],      bb_local[o], acc);
            acc = fmaf(Wb_fuse[k * 2 * NC + NC + o], bb_tri[o],   acc);
        }
#pragma unroll
        for (int off = 16; off; off >>= 1)
            acc += __shfl_xor_sync(0xffffffffu, acc, off);
        if (lane == 0)
            g_cb[k] = acc + ba_fuse[k] + bb_fuse[k];
    }
}

// ---------------------------------------------------------------------------
// Kernel 2: bulk-async (TMA-path) gather + fused dot.
// Warp owns a 2-edge group; lane 0 issues 10 x 512B cp.async.bulk into a
// 2-deep smem ring; mbarrier expect_tx completion; compute via LDS.128.
// Lane 0-15 -> tensor0 channels 8L.., lane 16-31 -> tensor1.
// ---------------------------------------------------------------------------
__device__ __forceinline__ unsigned smem_u32(const void* p)
{
    unsigned a;
    asm("{ .reg .u64 t; cvta.to.shared.u64 t, %1; cvt.u32.u64 %0, t; }"
        : "=r"(a) : "l"(p));
    return a;
}

__device__ __forceinline__ __half2 u2h(const unsigned& u)
{
    return *reinterpret_cast<const __half2*>(&u);
}

__device__ __forceinline__ void mbar_wait(unsigned mbar, int parity)
{
    asm volatile(
        "{\n\t"
        ".reg .pred P;\n\t"
        "W_%=:\n\t"
        "mbarrier.try_wait.parity.acquire.cta.shared::cta.b64 P, [%0], %1, 0x989680;\n\t"
        "@P bra D_%=;\n\t"
        "bra W_%=;\n\t"
        "D_%=:\n\t"
        "}"
        :: "r"(mbar), "r"(parity) : "memory");
}

// lane 0: issue 10 x 512B bulk copies of group (b, eb) into stage at dst
__device__ __forceinline__ void issue_group(
    int b, int eb, const int4 ga, const int4 gb,
    unsigned dst, unsigned mbar)
{
    asm volatile(
        "mbarrier.arrive.expect_tx.shared.b64 _, [%0], %1;"
        :: "r"(mbar), "r"(STAGE_BYTES) : "memory");
    const char* base = reinterpret_cast<const char*>(g_xti)
                     + (size_t)b * NE * 512;
    const int rows[10] = { eb,     ga.x, ga.y, ga.z, ga.w,
                           eb + 1, gb.x, gb.y, gb.z, gb.w };
#pragma unroll
    for (int r = 0; r < 10; r++) {
        const char* src = base + (size_t)rows[r] * 512;
        asm volatile(
            "cp.async.bulk.shared::cluster.global.mbarrier::complete_tx::bytes "
            "[%0], [%1], %2, [%3];"
            :: "r"(dst + r * 512), "l"(src), "r"(512), "r"(mbar) : "memory");
    }
}

__device__ __forceinline__ void edge_dot(
    const uint4 r0, const uint4 r1, const uint4 r2,
    const uint4 r3, const uint4 r4,
    const __half2 Vp[4][15], float* __restrict__ res)
{
    const __half2 z = __float2half2_rn(0.f);
    __half2 A0 = z, A1 = z, A2 = z, B0 = z, B1 = z, B2 = z;

#define DO_SLOT(j, X0, X1, X2, X3, X4, P0, P1, P2)                        \
    {                                                                     \
        __half2 G0 = u2h(X0);                                             \
        __half2 n1 = u2h(X1), n2 = u2h(X2), n3 = u2h(X3), n4 = u2h(X4);   \
        __half2 G1 = __hadd2(n1, n3), G2 = __hadd2(n2, n4);               \
        __half2 G3 = __habs2(__hsub2(n1, n3));                            \
        __half2 G4 = __habs2(__hsub2(n2, n4));                            \
        P0 = __hfma2(Vp[j][0],  G0, P0);                                  \
        P1 = __hfma2(Vp[j][1],  G0, P1);                                  \
        P2 = __hfma2(Vp[j][2],  G0, P2);                                  \
        P0 = __hfma2(Vp[j][3],  G1, P0);                                  \
        P1 = __hfma2(Vp[j][4],  G1, P1);                                  \
        P2 = __hfma2(Vp[j][5],  G1, P2);                                  \
        P0 = __hfma2(Vp[j][6],  G2, P0);                                  \
        P1 = __hfma2(Vp[j][7],  G2, P1);                                  \
        P2 = __hfma2(Vp[j][8],  G2, P2);                                  \
        P0 = __hfma2(Vp[j][9],  G3, P0);                                  \
        P1 = __hfma2(Vp[j][10], G3, P1);                                  \
        P2 = __hfma2(Vp[j][11], G3, P2);                                  \
        P0 = __hfma2(Vp[j][12], G4, P0);                                  \
        P1 = __hfma2(Vp[j][13], G4, P1);                                  \
        P2 = __hfma2(Vp[j][14], G4, P2);                                  \
    }

    DO_SLOT(0, r0.x, r1.x, r2.x, r3.x, r4.x, A0, A1, A2)
    DO_SLOT(1, r0.y, r1.y, r2.y, r3.y, r4.y, A0, A1, A2)
    DO_SLOT(2, r0.z, r1.z, r2.z, r3.z, r4.z, B0, B1, B2)
    DO_SLOT(3, r0.w, r1.w, r2.w, r3.w, r4.w, B0, B1, B2)
#undef DO_SLOT

    float2 a0 = __half22float2(A0), b0 = __half22float2(B0);
    float2 a1 = __half22float2(A1), b1 = __half22float2(B1);
    float2 a2 = __half22float2(A2), b2 = __half22float2(B2);
    res[0] = (a0.x + a0.y) + (b0.x + b0.y);
    res[1] = (a1.x + a1.y) + (b1.x + b1.y);
    res[2] = (a2.x + a2.y) + (b2.x + b2.y);
}

__global__ void __launch_bounds__(256, 2)
mesh_main_kernel(const int* __restrict__ gemm, float* __restrict__ out)
{
    extern __shared__ char sm_buf[];
    const int lane = threadIdx.x & 31;
    const int wid  = threadIdx.x >> 5;
    char* buf = sm_buf + wid * WARP_BUF;
    const unsigned buf_u32 = smem_u32(buf);
    const unsigned mbar0 = smem_u32(sm_buf + DATA_BYTES) + wid * 16;

    // init mbarriers (one per warp per stage), arrive count 1
    if (lane == 0) {
        asm volatile("mbarrier.init.shared.b64 [%0], %1;"
                     :: "r"(mbar0), "r"(1) : "memory");
        asm volatile("mbarrier.init.shared.b64 [%0], %1;"
                     :: "r"(mbar0 + 8), "r"(1) : "memory");
    }
    __syncthreads();

    // lane's tensor + channel base; weights: 60 half2 regs
    const int lt = lane >> 4;
    const int lc = (lane & 15) * 8;
    __half2 Vp[4][15];
#pragma unroll
    for (int j = 0; j < 4; j++) {
        const float* r0 = g_V[lt][lc + 2 * j];
        const float* r1 = g_V[lt][lc + 2 * j + 1];
#pragma unroll
        for (int sk = 0; sk < 15; sk++)
            Vp[j][sk] = __floats2half2_rn(r0[sk], r1[sk]);
    }
    float cbk = (lane < 6) ? g_cb[lane % 3] : 0.f;

    const int4* __restrict__ gi4 = reinterpret_cast<const int4*>(gemm);
    const int gw = blockIdx.x * 8 + wid;
    const int W  = gridDim.x * 8;

    int g  = gw;
    int b  = (2 * g >= NE) ? 1 : 0;
    int eb = 2 * g - b * NE;
    {
        int4 ga = gi4[(size_t)b * NE + eb];
        int4 gb = gi4[(size_t)b * NE + eb + 1];
        if (lane == 0) issue_group(b, eb, ga, gb, buf_u32, mbar0);
    }

    // next group's indices (clamped)
    int gnc = ((g + W) < GROUPS2) ? (g + W) : gw;
    int bn  = (2 * gnc >= NE) ? 1 : 0;
    int ebn = 2 * gnc - bn * NE;
    int4 gan = gi4[(size_t)bn * NE + ebn];
    int4 gbn = gi4[(size_t)bn * NE + ebn + 1];

    int s = 0;
    int ph[2] = {0, 0};
    while (true) {
        const bool has_next = (g + W) < GROUPS2;

        // issue next group into the other stage
        if (lane == 0)
            issue_group(bn, ebn, gan, gbn,
                        buf_u32 + (s ^ 1) * STAGE_BYTES,
                        mbar0 + (s ^ 1) * 8);

        // prefetch indices two groups ahead
        const int gn2c = ((g + 2 * W) < GROUPS2) ? (g + 2 * W) : gw;
        const int bn2  = (2 * gn2c >= NE) ? 1 : 0;
        const int ebn2 = 2 * gn2c - bn2 * NE;
        const int4 ga2 = gi4[(size_t)bn2 * NE + ebn2];
        const int4 gb2 = gi4[(size_t)bn2 * NE + ebn2 + 1];

        // wait for the current stage
        mbar_wait(mbar0 + s * 8, ph[s]);
        ph[s] ^= 1;

        // compute current stage
        float res[6];
#pragma unroll
        for (int u = 0; u < 2; u++) {
            const char* p = buf + s * STAGE_BYTES + u * 5 * 512 + lane * 16;
            uint4 r0 = *reinterpret_cast<const uint4*>(p);
            uint4 r1 = *reinterpret_cast<const uint4*>(p + 512);
            uint4 r2 = *reinterpret_cast<const uint4*>(p + 1024);
            uint4 r3 = *reinterpret_cast<const uint4*>(p + 1536);
            uint4 r4 = *reinterpret_cast<const uint4*>(p + 2048);
            edge_dot(r0, r1, r2, r3, r4, Vp, res + 3 * u);
        }

#pragma unroll
        for (int off = 16; off; off >>= 1)
#pragma unroll
            for (int r = 0; r < 6; r++)
                res[r] += __shfl_xor_sync(0xffffffffu, res[r], off);

        if (lane < 6) {
            const int u = lane / 3;
            const int k = lane - 3 * u;
            out[((size_t)b * 3 + k) * NE + eb + u] = res[lane] + cbk;
        }
        __syncwarp();

        if (!has_next) break;
        g += W;  b = bn;  eb = ebn;
        bn = bn2; ebn = ebn2; gan = ga2; gbn = gb2;
        s ^= 1;
    }

    // drain the last issued (unconsumed) stage before exit
    mbar_wait(mbar0 + (s ^ 1) * 8, ph[s ^ 1]);
}

// ---------------------------------------------------------------------------
extern "C" void kernel_launch(void* const* d_in, const int* in_sizes, int n_in,
                              void* d_out, int out_size)
{
    const float* x_0      = (const float*)d_in[0];
    const float* x_1      = (const float*)d_in[1];
    const int*   gemm     = (const int*)  d_in[2];
    const float* Wa_local = (const float*)d_in[3];
    const float* ba_local = (const float*)d_in[4];
    const float* Wb_local = (const float*)d_in[5];
    const float* bb_local = (const float*)d_in[6];
    const float* Wa_tri   = (const float*)d_in[7];
    const float* ba_tri   = (const float*)d_in[8];
    const float* Wb_tri   = (const float*)d_in[9];
    const float* bb_tri   = (const float*)d_in[10];
    const float* Wa_fuse  = (const float*)d_in[11];
    const float* ba_fuse  = (const float*)d_in[12];
    const float* Wb_fuse  = (const float*)d_in[13];
    const float* bb_fuse  = (const float*)d_in[14];
    float* out = (float*)d_out;

    static bool attr_set = false;
    if (!attr_set) {
        cudaFuncSetAttribute(mesh_main_kernel,
                             cudaFuncAttributeMaxDynamicSharedMemorySize,
                             SMEM_MAIN);
        attr_set = true;
    }

    prep_kernel<<<TR_BLOCKS + W_BLOCKS, 256>>>(
        x_0, x_1,
        Wa_local, ba_local, Wb_local, bb_local,
        Wa_tri, ba_tri, Wb_tri, bb_tri,
        Wa_fuse, ba_fuse, Wb_fuse, bb_fuse);

    mesh_main_kernel<<<296, 256, SMEM_MAIN>>>(gemm, out);
}

// round 15
// speedup vs baseline: 1.0396x; 1.0396x over previous
#include <cuda_runtime.h>
#include <cuda_fp16.h>
#include <cstddef>

#define NB 2
#define NC 128
#define TWOC 256
#define NE 60000
#define ETILES (NE / 32)
#define TR_BLOCKS (2 * NB * 2 * ETILES)              // 15000 transpose tiles
#define W_WARPS   (2 * NC * 15 + 3)
#define W_BLOCKS  ((W_WARPS + 7) / 8)                // 481
#define GROUPS4   (NB * NE / 4)                      // 30000 4-edge groups

// Transposed inputs in fp16, tensor-interleaved: [b][e][tensor][c] (512B/edge)
__device__ __half g_xti[(size_t)NB * NE * TWOC];
// Effective fused weights: [branch][c][s*3+k] padded to 16
__device__ float g_V[2][NC][16];
__device__ float g_cb[3];
// Precontracted self contribution: P0[b*NE+e] = {k0,k1,k2,pad}
__device__ float4 g_P0[(size_t)NB * NE];
// ordering flags (self-resetting each launch for graph-replay determinism)
__device__ int g_doneV = 0;
__device__ int g_doneT = 0;
__device__ volatile int g_vflag = 0;

// ---------------------------------------------------------------------------
// Kernel 1 (fused):
//  blocks [0, W_BLOCKS):       zero P0 + fold weights -> release flag
//  blocks [W_BLOCKS, +TR_BLOCKS): transpose tile, then (after flag) compute
//                               P0 partial dots from the smem tile (atomicAdd)
// ---------------------------------------------------------------------------
__global__ void __launch_bounds__(256)
prep_kernel(const float* __restrict__ x0, const float* __restrict__ x1,
    const float* __restrict__ Wa_local, const float* __restrict__ ba_local,
    const float* __restrict__ Wb_local, const float* __restrict__ bb_local,
    const float* __restrict__ Wa_tri,   const float* __restrict__ ba_tri,
    const float* __restrict__ Wb_tri,   const float* __restrict__ bb_tri,
    const float* __restrict__ Wa_fuse,  const float* __restrict__ ba_fuse,
    const float* __restrict__ Wb_fuse,  const float* __restrict__ bb_fuse)
{
    const int lane = threadIdx.x & 31;

    if (blockIdx.x < W_BLOCKS) {
        // ---- zero P0 chunk (481*256 = 123136 >= 120000) ----
        const int zi = blockIdx.x * 256 + threadIdx.x;
        if (zi < NB * NE)
            g_P0[zi] = make_float4(0.f, 0.f, 0.f, 0.f);

        // ---- weight folding: one warp per output ----
        const int w = blockIdx.x * 8 + (threadIdx.x >> 5);
        if (w < 2 * NC * 15) {
            const int t   = w / (NC * 15);
            const int rem = w - t * (NC * 15);
            const int c   = rem / 15;
            const int sk  = rem - c * 15;
            const int s   = sk / 3;
            const int k   = sk - s * 3;
            const float* Wf = t ? Wb_fuse  : Wa_fuse;
            const float* Wt = t ? Wb_tri   : Wa_tri;
            const float* Wl = t ? Wb_local : Wa_local;
            float acc = 0.f;
#pragma unroll
            for (int j = 0; j < 4; j++) {
                int o = lane + 32 * j;
                acc = fmaf(Wf[k * (2 * NC) + NC + o], Wt[(o * NC + c) * 5 + s], acc);
                if (s == 0)
                    acc = fmaf(Wf[k * (2 * NC) + o], Wl[o * NC + c], acc);
            }
#pragma unroll
            for (int off = 16; off; off >>= 1)
                acc += __shfl_xor_sync(0xffffffffu, acc, off);
            if (lane == 0) {
                g_V[t][c][sk] = acc;
                if (sk == 0) g_V[t][c][15] = 0.f;
            }
        } else if (w < 2 * NC * 15 + 3) {
            const int k = w - 2 * NC * 15;
            float acc = 0.f;
#pragma unroll
            for (int j = 0; j < 4; j++) {
                int o = lane + 32 * j;
                acc = fmaf(Wa_fuse[k * 2 * NC + o],      ba_local[o], acc);
                acc = fmaf(Wa_fuse[k * 2 * NC + NC + o], ba_tri[o],   acc);
                acc = fmaf(Wb_fuse[k * 2 * NC + o],      bb_local[o], acc);
                acc = fmaf(Wb_fuse[k * 2 * NC + NC + o], bb_tri[o],   acc);
            }
#pragma unroll
            for (int off = 16; off; off >>= 1)
                acc += __shfl_xor_sync(0xffffffffu, acc, off);
            if (lane == 0)
                g_cb[k] = acc + ba_fuse[k] + bb_fuse[k];
        }

        __syncthreads();
        if (threadIdx.x == 0) {
            __threadfence();
            int old = atomicAdd(&g_doneV, 1);
            if (old == W_BLOCKS - 1) {
                __threadfence();
                g_vflag = 1;
            }
        }
        return;
    }

    // ---- transpose tile + P0 partial ----
    __shared__ __half tile[32][66];
    __shared__ float  Vs[64][3];

    int bx = blockIdx.x - W_BLOCKS;
    const int eb = bx % ETILES;  bx /= ETILES;
    const int ch = bx & 1;       bx >>= 1;
    const int b  = bx & 1;
    const int tensor = bx >> 1;
    const float* __restrict__ src = tensor ? x1 : x0;
    const int e0 = eb * 32, c0 = ch * 64;
    const int tx = threadIdx.x & 31;
    const int ty = threadIdx.x >> 5;

#pragma unroll
    for (int i = 0; i < 8; i++) {
        int cl = ty + 8 * i;
        tile[tx][cl] = __float2half_rn(
            src[((size_t)b * NC + c0 + cl) * NE + e0 + tx]);
    }
    __syncthreads();
#pragma unroll
    for (int it = 0; it < 4; it++) {
        int e = ty * 4 + it;
        unsigned v = *reinterpret_cast<const unsigned*>(&tile[e][2 * tx]);
        *reinterpret_cast<unsigned*>(
            g_xti + ((size_t)(b * NE + e0 + e)) * TWOC
                  + tensor * NC + c0 + 2 * tx) = v;
    }

    // wait for weights + P0-zero to be globally visible
    if (threadIdx.x == 0) {
        while (g_vflag == 0) __nanosleep(128);
    }
    __syncthreads();

    // stage this tile's V slice (s=0)
    if (threadIdx.x < 192)
        Vs[threadIdx.x / 3][threadIdx.x % 3] =
            g_V[tensor][c0 + threadIdx.x / 3][threadIdx.x % 3];
    __syncthreads();

    // partial P0 dots: warp ty<3 handles k=ty, lane tx = edge e0+tx
    if (ty < 3) {
        float acc = 0.f;
#pragma unroll
        for (int c = 0; c < 64; c++)
            acc = fmaf(Vs[c][ty], __half2float(tile[tx][c]), acc);
        atomicAdd(reinterpret_cast<float*>(&g_P0[(size_t)b * NE + e0 + tx]) + ty,
                  acc);
    }

    // self-resetting completion counter (for graph replays)
    __syncthreads();
    if (threadIdx.x == 0) {
        int old = atomicAdd(&g_doneT, 1);
        if (old == TR_BLOCKS - 1) {
            g_doneV = 0;
            g_doneT = 0;
            __threadfence();
            g_vflag = 0;
        }
    }
}

// ---------------------------------------------------------------------------
// Kernel 2: main gather + fused dot. One warp per 4 edges; per edge only the
// 4 NEIGHBOR rows are gathered (self contribution precontracted into P0).
// Lane 0-15 -> tensor0 channels 8L.., lane 16-31 -> tensor1.
// ---------------------------------------------------------------------------
__device__ __forceinline__ __half2 u2h(const unsigned& u)
{
    return *reinterpret_cast<const __half2*>(&u);
}

__device__ __forceinline__ void edge_dot(
    const uint4 r1, const uint4 r2, const uint4 r3, const uint4 r4,
    const __half2 Vp[4][12], float* __restrict__ res)
{
    const __half2 z = __float2half2_rn(0.f);
    __half2 A0 = z, A1 = z, A2 = z, B0 = z, B1 = z, B2 = z;

#define DO_SLOT(j, X1, X2, X3, X4, P0, P1, P2)                            \
    {                                                                     \
        __half2 n1 = u2h(X1), n2 = u2h(X2), n3 = u2h(X3), n4 = u2h(X4);   \
        __half2 G1 = __hadd2(n1, n3), G2 = __hadd2(n2, n4);               \
        __half2 G3 = __habs2(__hsub2(n1, n3));                            \
        __half2 G4 = __habs2(__hsub2(n2, n4));                            \
        P0 = __hfma2(Vp[j][0],  G1, P0);                                  \
        P1 = __hfma2(Vp[j][1],  G1, P1);                                  \
        P2 = __hfma2(Vp[j][2],  G1, P2);                                  \
        P0 = __hfma2(Vp[j][3],  G2, P0);                                  \
        P1 = __hfma2(Vp[j][4],  G2, P1);                                  \
        P2 = __hfma2(Vp[j][5],  G2, P2);                                  \
        P0 = __hfma2(Vp[j][6],  G3, P0);                                  \
        P1 = __hfma2(Vp[j][7],  G3, P1);                                  \
        P2 = __hfma2(Vp[j][8],  G3, P2);                                  \
        P0 = __hfma2(Vp[j][9],  G4, P0);                                  \
        P1 = __hfma2(Vp[j][10], G4, P1);                                  \
        P2 = __hfma2(Vp[j][11], G4, P2);                                  \
    }

    DO_SLOT(0, r1.x, r2.x, r3.x, r4.x, A0, A1, A2)
    DO_SLOT(1, r1.y, r2.y, r3.y, r4.y, A0, A1, A2)
    DO_SLOT(2, r1.z, r2.z, r3.z, r4.z, B0, B1, B2)
    DO_SLOT(3, r1.w, r2.w, r3.w, r4.w, B0, B1, B2)
#undef DO_SLOT

    float2 a0 = __half22float2(A0), b0 = __half22float2(B0);
    float2 a1 = __half22float2(A1), b1 = __half22float2(B1);
    float2 a2 = __half22float2(A2), b2 = __half22float2(B2);
    res[0] = (a0.x + a0.y) + (b0.x + b0.y);
    res[1] = (a1.x + a1.y) + (b1.x + b1.y);
    res[2] = (a2.x + a2.y) + (b2.x + b2.y);
}

// one PAIR of edges: 8 batched LDG.128 (neighbor rows only) -> res[0..5]
__device__ __forceinline__ void do_pair(
    const __half* __restrict__ base,
    const int4 gi0, const int4 gi1,
    const __half2 Vp[4][12], float* __restrict__ res)
{
    uint4 a1 = *reinterpret_cast<const uint4*>(base + (size_t)gi0.x * TWOC);
    uint4 a2 = *reinterpret_cast<const uint4*>(base + (size_t)gi0.y * TWOC);
    uint4 a3 = *reinterpret_cast<const uint4*>(base + (size_t)gi0.z * TWOC);
    uint4 a4 = *reinterpret_cast<const uint4*>(base + (size_t)gi0.w * TWOC);
    uint4 c1 = *reinterpret_cast<const uint4*>(base + (size_t)gi1.x * TWOC);
    uint4 c2 = *reinterpret_cast<const uint4*>(base + (size_t)gi1.y * TWOC);
    uint4 c3 = *reinterpret_cast<const uint4*>(base + (size_t)gi1.z * TWOC);
    uint4 c4 = *reinterpret_cast<const uint4*>(base + (size_t)gi1.w * TWOC);

    edge_dot(a1, a2, a3, a4, Vp, res);
    edge_dot(c1, c2, c3, c4, Vp, res + 3);
}

__global__ void __launch_bounds__(256, 2)
mesh_main_kernel(const int* __restrict__ gemm, float* __restrict__ out)
{
    const int lane = threadIdx.x & 31;
    const int gw   = blockIdx.x * 8 + (threadIdx.x >> 5);
    const int W    = gridDim.x * 8;

    const int lt = lane >> 4;              // tensor
    const int lc = (lane & 15) * 8;        // channel base (8 channels)

    // weights for s=1..4 only: 48 half2 regs
    __half2 Vp[4][12];
#pragma unroll
    for (int j = 0; j < 4; j++) {
        const float* r0 = g_V[lt][lc + 2 * j];
        const float* r1 = g_V[lt][lc + 2 * j + 1];
#pragma unroll
        for (int i = 0; i < 12; i++)
            Vp[j][i] = __floats2half2_rn(r0[3 + i], r1[3 + i]);
    }
    float cbk = (lane < 12) ? g_cb[lane % 3] : 0.f;

    const int4* __restrict__ gi4 = reinterpret_cast<const int4*>(gemm);

    int g = gw;
    if (g >= GROUPS4) return;

    int e0 = 4 * g;
    int b  = (e0 >= NE) ? 1 : 0;
    int eb = e0 - b * NE;
    int4 gA = gi4[(size_t)b * NE + eb];
    int4 gB = gi4[(size_t)b * NE + eb + 1];

    while (g < GROUPS4) {
        const int4 gC = gi4[(size_t)b * NE + eb + 2];
        const int4 gD = gi4[(size_t)b * NE + eb + 3];

        const int gn  = g + W;
        const int gnc = (gn < GROUPS4) ? gn : gw;
        const int e0n = 4 * gnc;
        const int bn  = (e0n >= NE) ? 1 : 0;
        const int ebn = e0n - bn * NE;
        const int4 gA_n = gi4[(size_t)bn * NE + ebn];
        const int4 gB_n = gi4[(size_t)bn * NE + ebn + 1];

        const __half* __restrict__ base =
            g_xti + (size_t)b * NE * TWOC + lane * 8;

        // precontracted self contribution (one 16B read per edge)
        float4 p0 = make_float4(0.f, 0.f, 0.f, 0.f);
        if (lane < 4)
            p0 = g_P0[(size_t)b * NE + eb + lane];

        float res[12];
        do_pair(base, gA, gB, Vp, res);
        do_pair(base, gC, gD, Vp, res + 6);

        if (lane < 4) {
            res[3 * lane + 0] += p0.x;
            res[3 * lane + 1] += p0.y;
            res[3 * lane + 2] += p0.z;
        }

#pragma unroll
        for (int off = 16; off; off >>= 1)
#pragma unroll
            for (int r = 0; r < 12; r++)
                res[r] += __shfl_xor_sync(0xffffffffu, res[r], off);

        if (lane < 12) {
            const int u = lane / 3;
            const int k = lane - 3 * u;
            out[((size_t)b * 3 + k) * NE + eb + u] = res[lane] + cbk;
        }

        g  = gn;
        b  = bn;
        eb = ebn;
        gA = gA_n;
        gB = gB_n;
    }
}

// ---------------------------------------------------------------------------
extern "C" void kernel_launch(void* const* d_in, const int* in_sizes, int n_in,
                              void* d_out, int out_size)
{
    const float* x_0      = (const float*)d_in[0];
    const float* x_1      = (const float*)d_in[1];
    const int*   gemm     = (const int*)  d_in[2];
    const float* Wa_local = (const float*)d_in[3];
    const float* ba_local = (const float*)d_in[4];
    const float* Wb_local = (const float*)d_in[5];
    const float* bb_local = (const float*)d_in[6];
    const float* Wa_tri   = (const float*)d_in[7];
    const float* ba_tri   = (const float*)d_in[8];
    const float* Wb_tri   = (const float*)d_in[9];
    const float* bb_tri   = (const float*)d_in[10];
    const float* Wa_fuse  = (const float*)d_in[11];
    const float* ba_fuse  = (const float*)d_in[12];
    const float* Wb_fuse  = (const float*)d_in[13];
    const float* bb_fuse  = (const float*)d_in[14];
    float* out = (float*)d_out;

    prep_kernel<<<W_BLOCKS + TR_BLOCKS, 256>>>(
        x_0, x_1,
        Wa_local, ba_local, Wb_local, bb_local,
        Wa_tri, ba_tri, Wb_tri, bb_tri,
        Wa_fuse, ba_fuse, Wb_fuse, bb_fuse);

    mesh_main_kernel<<<296, 256>>>(gemm, out);
}

// round 16
// speedup vs baseline: 1.1043x; 1.0622x over previous
#include <cuda_runtime.h>
#include <cuda_fp16.h>
#include <cstddef>

#define NB 2
#define NC 128
#define TWOC 256
#define NE 60000
#define ETILES (NE / 32)                             // 1875
#define TRB (2 * NB * ETILES)                        // 7500 full-channel tiles
#define W_WARPS   (2 * NC * 15 + 3)
#define W_BLOCKS  ((W_WARPS + 7) / 8)                // 481
#define GROUPS4   (NB * NE / 4)                      // 30000 4-edge groups

// Transposed inputs in fp16, tensor-interleaved: [b][e][tensor][c] (512B/edge)
__device__ __half g_xti[(size_t)NB * NE * TWOC];
// Effective fused weights: [branch][c][s*3+k] padded to 16
__device__ float g_V[2][NC][16];
__device__ float g_cb[3];
// Precontracted self contribution, tensor-split planes: [tensor][k][b*NE+e]
__device__ float g_P0t[2][3][(size_t)NB * NE];
// ordering flags (self-resetting each launch for graph-replay determinism)
__device__ int g_doneV = 0;
__device__ int g_doneT = 0;
__device__ volatile int g_vflag = 0;

// ---------------------------------------------------------------------------
// Kernel 1 (fused):
//  blocks [0, W_BLOCKS):  fold weights -> release flag
//  blocks [W_BLOCKS, +TRB): transpose a FULL-channel (128c x 32e) tile of one
//    (tensor,b), then (after flag) compute its P0 plane slice from smem.
//    No atomics anywhere; P0 stores are coalesced and exclusive.
// ---------------------------------------------------------------------------
__global__ void __launch_bounds__(256)
prep_kernel(const float* __restrict__ x0, const float* __restrict__ x1,
    const float* __restrict__ Wa_local, const float* __restrict__ ba_local,
    const float* __restrict__ Wb_local, const float* __restrict__ bb_local,
    const float* __restrict__ Wa_tri,   const float* __restrict__ ba_tri,
    const float* __restrict__ Wb_tri,   const float* __restrict__ bb_tri,
    const float* __restrict__ Wa_fuse,  const float* __restrict__ ba_fuse,
    const float* __restrict__ Wb_fuse,  const float* __restrict__ bb_fuse)
{
    const int lane = threadIdx.x & 31;

    if (blockIdx.x < W_BLOCKS) {
        // ---- weight folding: one warp per output ----
        const int w = blockIdx.x * 8 + (threadIdx.x >> 5);
        if (w < 2 * NC * 15) {
            const int t   = w / (NC * 15);
            const int rem = w - t * (NC * 15);
            const int c   = rem / 15;
            const int sk  = rem - c * 15;
            const int s   = sk / 3;
            const int k   = sk - s * 3;
            const float* Wf = t ? Wb_fuse  : Wa_fuse;
            const float* Wt = t ? Wb_tri   : Wa_tri;
            const float* Wl = t ? Wb_local : Wa_local;
            float acc = 0.f;
#pragma unroll
            for (int j = 0; j < 4; j++) {
                int o = lane + 32 * j;
                acc = fmaf(Wf[k * (2 * NC) + NC + o], Wt[(o * NC + c) * 5 + s], acc);
                if (s == 0)
                    acc = fmaf(Wf[k * (2 * NC) + o], Wl[o * NC + c], acc);
            }
#pragma unroll
            for (int off = 16; off; off >>= 1)
                acc += __shfl_xor_sync(0xffffffffu, acc, off);
            if (lane == 0) {
                g_V[t][c][sk] = acc;
                if (sk == 0) g_V[t][c][15] = 0.f;
            }
        } else if (w < 2 * NC * 15 + 3) {
            const int k = w - 2 * NC * 15;
            float acc = 0.f;
#pragma unroll
            for (int j = 0; j < 4; j++) {
                int o = lane + 32 * j;
                acc = fmaf(Wa_fuse[k * 2 * NC + o],      ba_local[o], acc);
                acc = fmaf(Wa_fuse[k * 2 * NC + NC + o], ba_tri[o],   acc);
                acc = fmaf(Wb_fuse[k * 2 * NC + o],      bb_local[o], acc);
                acc = fmaf(Wb_fuse[k * 2 * NC + NC + o], bb_tri[o],   acc);
            }
#pragma unroll
            for (int off = 16; off; off >>= 1)
                acc += __shfl_xor_sync(0xffffffffu, acc, off);
            if (lane == 0)
                g_cb[k] = acc + ba_fuse[k] + bb_fuse[k];
        }

        __syncthreads();
        if (threadIdx.x == 0) {
            __threadfence();
            int old = atomicAdd(&g_doneV, 1);
            if (old == W_BLOCKS - 1) {
                __threadfence();
                g_vflag = 1;
            }
        }
        return;
    }

    // ---- full-channel transpose tile + P0 plane slice ----
    __shared__ __half tile[32][130];          // [edge][channel], stride 130
    __shared__ float  psum[8][32][3];         // [part][edge][k]
    __shared__ float  Vs[NC][3];

    int bx = blockIdx.x - W_BLOCKS;
    const int eb = bx % ETILES;  bx /= ETILES;
    const int b  = bx & 1;
    const int tensor = bx >> 1;
    const float* __restrict__ src = tensor ? x1 : x0;
    const int e0 = eb * 32;
    const int tx = threadIdx.x & 31;
    const int ty = threadIdx.x >> 5;

    // load 128 channels x 32 edges, fp32 -> fp16 smem
#pragma unroll
    for (int i = 0; i < 16; i++) {
        int c = ty + 8 * i;
        tile[tx][c] = __float2half_rn(
            src[((size_t)b * NC + c) * NE + e0 + tx]);
    }
    __syncthreads();

    // store to interleaved xti: warp ty handles edges ty*4..ty*4+3,
    // each edge = 64 u32 (two coalesced 128B stores)
    {
        const half2* t2 = reinterpret_cast<const half2*>(&tile[0][0]);
#pragma unroll
        for (int it = 0; it < 4; it++) {
            int e = ty * 4 + it;
            unsigned v0 = *reinterpret_cast<const unsigned*>(&t2[e * 65 + tx]);
            unsigned v1 = *reinterpret_cast<const unsigned*>(&t2[e * 65 + 32 + tx]);
            unsigned* dst = reinterpret_cast<unsigned*>(
                g_xti + ((size_t)(b * NE + e0 + e)) * TWOC + tensor * NC);
            dst[tx]      = v0;
            dst[32 + tx] = v1;
        }
    }

    // wait for weights to be globally visible (released by wave-1 W blocks)
    if (threadIdx.x == 0) {
        while (g_vflag == 0) __nanosleep(128);
    }
    __syncthreads();

    // stage V slice (s=0): 128 channels x 3 k
    for (int i = threadIdx.x; i < NC * 3; i += 256)
        Vs[i / 3][i % 3] = g_V[tensor][i / 3][i % 3];
    __syncthreads();

    // partial dots: thread (tx,ty) handles edge tx, channels ty*16..ty*16+15
    {
        const half2* t2 = reinterpret_cast<const half2*>(&tile[0][0]);
        float a0 = 0.f, a1 = 0.f, a2 = 0.f;
#pragma unroll
        for (int j = 0; j < 8; j++) {
            float2 h = __half22float2(t2[tx * 65 + ty * 8 + j]);
            const int c = ty * 16 + 2 * j;
            a0 = fmaf(Vs[c][0], h.x, a0); a0 = fmaf(Vs[c + 1][0], h.y, a0);
            a1 = fmaf(Vs[c][1], h.x, a1); a1 = fmaf(Vs[c + 1][1], h.y, a1);
            a2 = fmaf(Vs[c][2], h.x, a2); a2 = fmaf(Vs[c + 1][2], h.y, a2);
        }
        psum[ty][tx][0] = a0;
        psum[ty][tx][1] = a1;
        psum[ty][tx][2] = a2;
    }
    __syncthreads();

    // reduce 8 parts; warps 0-2 (k=ty), lane tx = edge; coalesced plane store
    if (ty < 3) {
        float acc = 0.f;
#pragma unroll
        for (int p = 0; p < 8; p++)
            acc += psum[p][tx][ty];
        g_P0t[tensor][ty][(size_t)b * NE + e0 + tx] = acc;
    }

    // self-resetting completion counter (for graph replays)
    __syncthreads();
    if (threadIdx.x == 0) {
        int old = atomicAdd(&g_doneT, 1);
        if (old == TRB - 1) {
            g_doneV = 0;
            g_doneT = 0;
            __threadfence();
            g_vflag = 0;
        }
    }
}

// ---------------------------------------------------------------------------
// Kernel 2: main gather + fused dot. One warp per 4 edges; per edge only the
// 4 NEIGHBOR rows are gathered (self contribution precontracted into P0t).
// Lane 0-15 -> tensor0 channels 8L.., lane 16-31 -> tensor1.
// ---------------------------------------------------------------------------
__device__ __forceinline__ __half2 u2h(const unsigned& u)
{
    return *reinterpret_cast<const __half2*>(&u);
}

__device__ __forceinline__ void edge_dot(
    const uint4 r1, const uint4 r2, const uint4 r3, const uint4 r4,
    const __half2 Vp[4][12], float* __restrict__ res)
{
    const __half2 z = __float2half2_rn(0.f);
    __half2 A0 = z, A1 = z, A2 = z, B0 = z, B1 = z, B2 = z;

#define DO_SLOT(j, X1, X2, X3, X4, P0, P1, P2)                            \
    {                                                                     \
        __half2 n1 = u2h(X1), n2 = u2h(X2), n3 = u2h(X3), n4 = u2h(X4);   \
        __half2 G1 = __hadd2(n1, n3), G2 = __hadd2(n2, n4);               \
        __half2 G3 = __habs2(__hsub2(n1, n3));                            \
        __half2 G4 = __habs2(__hsub2(n2, n4));                            \
        P0 = __hfma2(Vp[j][0],  G1, P0);                                  \
        P1 = __hfma2(Vp[j][1],  G1, P1);                                  \
        P2 = __hfma2(Vp[j][2],  G1, P2);                                  \
        P0 = __hfma2(Vp[j][3],  G2, P0);                                  \
        P1 = __hfma2(Vp[j][4],  G2, P1);                                  \
        P2 = __hfma2(Vp[j][5],  G2, P2);                                  \
        P0 = __hfma2(Vp[j][6],  G3, P0);                                  \
        P1 = __hfma2(Vp[j][7],  G3, P1);                                  \
        P2 = __hfma2(Vp[j][8],  G3, P2);                                  \
        P0 = __hfma2(Vp[j][9],  G4, P0);                                  \
        P1 = __hfma2(Vp[j][10], G4, P1);                                  \
        P2 = __hfma2(Vp[j][11], G4, P2);                                  \
    }

    DO_SLOT(0, r1.x, r2.x, r3.x, r4.x, A0, A1, A2)
    DO_SLOT(1, r1.y, r2.y, r3.y, r4.y, A0, A1, A2)
    DO_SLOT(2, r1.z, r2.z, r3.z, r4.z, B0, B1, B2)
    DO_SLOT(3, r1.w, r2.w, r3.w, r4.w, B0, B1, B2)
#undef DO_SLOT

    float2 a0 = __half22float2(A0), b0 = __half22float2(B0);
    float2 a1 = __half22float2(A1), b1 = __half22float2(B1);
    float2 a2 = __half22float2(A2), b2 = __half22float2(B2);
    res[0] = (a0.x + a0.y) + (b0.x + b0.y);
    res[1] = (a1.x + a1.y) + (b1.x + b1.y);
    res[2] = (a2.x + a2.y) + (b2.x + b2.y);
}

// one PAIR of edges: 8 batched LDG.128 (neighbor rows only) -> res[0..5]
__device__ __forceinline__ void do_pair(
    const __half* __restrict__ base,
    const int4 gi0, const int4 gi1,
    const __half2 Vp[4][12], float* __restrict__ res)
{
    uint4 a1 = *reinterpret_cast<const uint4*>(base + (size_t)gi0.x * TWOC);
    uint4 a2 = *reinterpret_cast<const uint4*>(base + (size_t)gi0.y * TWOC);
    uint4 a3 = *reinterpret_cast<const uint4*>(base + (size_t)gi0.z * TWOC);
    uint4 a4 = *reinterpret_cast<const uint4*>(base + (size_t)gi0.w * TWOC);
    uint4 c1 = *reinterpret_cast<const uint4*>(base + (size_t)gi1.x * TWOC);
    uint4 c2 = *reinterpret_cast<const uint4*>(base + (size_t)gi1.y * TWOC);
    uint4 c3 = *reinterpret_cast<const uint4*>(base + (size_t)gi1.z * TWOC);
    uint4 c4 = *reinterpret_cast<const uint4*>(base + (size_t)gi1.w * TWOC);

    edge_dot(a1, a2, a3, a4, Vp, res);
    edge_dot(c1, c2, c3, c4, Vp, res + 3);
}

__global__ void __launch_bounds__(256, 2)
mesh_main_kernel(const int* __restrict__ gemm, float* __restrict__ out)
{
    const int lane = threadIdx.x & 31;
    const int gw   = blockIdx.x * 8 + (threadIdx.x >> 5);
    const int W    = gridDim.x * 8;

    const int lt = lane >> 4;              // tensor
    const int lc = (lane & 15) * 8;        // channel base (8 channels)

    // weights for s=1..4 only: 48 half2 regs
    __half2 Vp[4][12];
#pragma unroll
    for (int j = 0; j < 4; j++) {
        const float* r0 = g_V[lt][lc + 2 * j];
        const float* r1 = g_V[lt][lc + 2 * j + 1];
#pragma unroll
        for (int i = 0; i < 12; i++)
            Vp[j][i] = __floats2half2_rn(r0[3 + i], r1[3 + i]);
    }
    float cbk = (lane < 12) ? g_cb[lane % 3] : 0.f;

    // this lane's tensor's P0 planes
    const float* __restrict__ p0b = &g_P0t[lt][0][0];

    const int4* __restrict__ gi4 = reinterpret_cast<const int4*>(gemm);

    int g = gw;
    if (g >= GROUPS4) return;

    int e0 = 4 * g;
    int b  = (e0 >= NE) ? 1 : 0;
    int eb = e0 - b * NE;
    int4 gA = gi4[(size_t)b * NE + eb];
    int4 gB = gi4[(size_t)b * NE + eb + 1];

    while (g < GROUPS4) {
        const int4 gC = gi4[(size_t)b * NE + eb + 2];
        const int4 gD = gi4[(size_t)b * NE + eb + 3];

        const int gn  = g + W;
        const int gnc = (gn < GROUPS4) ? gn : gw;
        const int e0n = 4 * gnc;
        const int bn  = (e0n >= NE) ? 1 : 0;
        const int ebn = e0n - bn * NE;
        const int4 gA_n = gi4[(size_t)bn * NE + ebn];
        const int4 gB_n = gi4[(size_t)bn * NE + ebn + 1];

        const __half* __restrict__ base =
            g_xti + (size_t)b * NE * TWOC + lane * 8;

        float res[12];
        do_pair(base, gA, gB, Vp, res);
        do_pair(base, gC, gD, Vp, res + 6);

        // fold in this tensor's precontracted self contribution
        {
            const int u = lane & 15;
            if (u < 4) {
                const size_t idx = (size_t)b * NE + eb + u;
                res[3 * u + 0] += p0b[idx];
                res[3 * u + 1] += p0b[(size_t)NB * NE + idx];
                res[3 * u + 2] += p0b[2 * (size_t)NB * NE + idx];
            }
        }

#pragma unroll
        for (int off = 16; off; off >>= 1)
#pragma unroll
            for (int r = 0; r < 12; r++)
                res[r] += __shfl_xor_sync(0xffffffffu, res[r], off);

        if (lane < 12) {
            const int u = lane / 3;
            const int k = lane - 3 * u;
            out[((size_t)b * 3 + k) * NE + eb + u] = res[lane] + cbk;
        }

        g  = gn;
        b  = bn;
        eb = ebn;
        gA = gA_n;
        gB = gB_n;
    }
}

// ---------------------------------------------------------------------------
extern "C" void kernel_launch(void* const* d_in, const int* in_sizes, int n_in,
                              void* d_out, int out_size)
{
    const float* x_0      = (const float*)d_in[0];
    const float* x_1      = (const float*)d_in[1];
    const int*   gemm     = (const int*)  d_in[2];
    const float* Wa_local = (const float*)d_in[3];
    const float* ba_local = (const float*)d_in[4];
    const float* Wb_local = (const float*)d_in[5];
    const float* bb_local = (const float*)d_in[6];
    const float* Wa_tri   = (const float*)d_in[7];
    const float* ba_tri   = (const float*)d_in[8];
    const float* Wb_tri   = (const float*)d_in[9];
    const float* bb_tri   = (const float*)d_in[10];
    const float* Wa_fuse  = (const float*)d_in[11];
    const float* ba_fuse  = (const float*)d_in[12];
    const float* Wb_fuse  = (const float*)d_in[13];
    const float* bb_fuse  = (const float*)d_in[14];
    float* out = (float*)d_out;

    prep_kernel<<<W_BLOCKS + TRB, 256>>>(
        x_0, x_1,
        Wa_local, ba_local, Wb_local, bb_local,
        Wa_tri, ba_tri, Wb_tri, bb_tri,
        Wa_fuse, ba_fuse, Wb_fuse, bb_fuse);

    mesh_main_kernel<<<296, 256>>>(gemm, out);
}